// round 13
// baseline (speedup 1.0000x reference)
#include <cuda_runtime.h>

#define BB 256
#define TT 1024
#define DD 128
#define LL 16
#define OO 256

// ---- recurrence geometry (R7/R11 tiling): 256 thr = 8 warps = 4 k-chunks x
// 2 o-halves; thread: 64 k x 4 o; 48 k in regs, 16 k via smem.
// NEW: batch-staggered segments — phase1(X) overlapped with phase2(Y).
#define NTHR 256
#define RSM_TSTRIDE 272     // 32 u64 data + 2 u64 pad per thread

#define PA_OFF   0          // partial_A [4 chunk][256 o] f32 = 4 KB
#define PB_OFF   4096       // partial_B                      = 4 KB
#define S_OFF    8192       // state [2 batch][256] f32       = 2 KB
#define RSM_OFF  12288      // Rsm: 256 * 272 = 69632 B
#define SMEM_BYTES (RSM_OFF + NTHR * RSM_TSTRIDE)   // 81920 B

// +OO pad: staggered prefetch touches agg index (b0+1, t=TT) == end of array.
__device__ float g_agg[(size_t)BB * TT * OO + OO];

#define FMA2(acc, a, b) asm("fma.rn.f32x2 %0, %1, %2, %0;" : "+l"(acc) : "l"(a), "l"(b))

__device__ __forceinline__ void lds_v2u64(unsigned long long& a, unsigned long long& b,
                                          unsigned int addr) {
    asm volatile("ld.shared.v2.u64 {%0, %1}, [%2];" : "=l"(a), "=l"(b) : "r"(addr));
}
__device__ __forceinline__ float lds_f32(unsigned int addr) {
    float v; asm volatile("ld.shared.f32 %0, [%1];" : "=f"(v) : "r"(addr)); return v;
}
__device__ __forceinline__ void sts_f32(unsigned int addr, float v) {
    asm volatile("st.shared.f32 [%0], %1;" :: "r"(addr), "f"(v));
}
__device__ __forceinline__ void sts_u64(unsigned int addr, unsigned long long v) {
    asm volatile("st.shared.u64 [%0], %1;" :: "r"(addr), "l"(v));
}

// ---------------------------------------------------------------------------
// Kernel 1: agg[b,t,o] — R11 VERBATIM (measured 159 us; R12's packed variant
// regressed to 200 us and is reverted).
// ---------------------------------------------------------------------------
__global__ void __launch_bounds__(256) act_agg_kernel(
    const float* __restrict__ x, const float* __restrict__ subW,
    const float* __restrict__ subb, const float* __restrict__ aggW)
{
    __shared__ float xs[64][DD];
    __shared__ float ws[LL][DD + 4];
    __shared__ float as_[64][LL + 1];

    const int tid = threadIdx.x;
    const size_t row0 = (size_t)blockIdx.x * 64;

    for (int i = tid; i < LL * DD; i += 256) ws[i / DD][i % DD] = subW[i];
    {
        const float4* xg = (const float4*)(x + row0 * DD);
        float4* xs4 = (float4*)&xs[0][0];
#pragma unroll
        for (int i = 0; i < 8; i++) xs4[tid + 256 * i] = xg[tid + 256 * i];
    }
    __syncthreads();

    {
        const int l = tid & 15;
        const int rb = tid >> 4;
        const float bias = subb[l];
        const ulonglong2* wr = (const ulonglong2*)&ws[l][0];
#pragma unroll
        for (int it = 0; it < 4; it++) {
            const int r = rb + 16 * it;
            const ulonglong2* xr = (const ulonglong2*)&xs[r][0];
            unsigned long long acc = 0ULL;
#pragma unroll
            for (int i = 0; i < 32; i++) {
                ulonglong2 a = xr[i], b = wr[i];
                FMA2(acc, a.x, b.x);
                FMA2(acc, a.y, b.y);
            }
            float lo, hi;
            asm("mov.b64 {%0, %1}, %2;" : "=f"(lo), "=f"(hi) : "l"(acc));
            const float s = lo + hi + bias;
            float v;
            const int m = l & 3;
            if (m == 0)      v = tanhf(s);
            else if (m == 1) v = fmaxf(s, 0.f);
            else if (m == 2) v = 1.f / (1.f + expf(-s));
            else             v = s;
            as_[r][l] = v;
        }
    }
    __syncthreads();

    {
        const int oq = tid & 63;
        const int rq = tid >> 6;
        const int o0 = oq * 4;
        float4 wc[LL];
#pragma unroll
        for (int l = 0; l < LL; l++) wc[l] = *(const float4*)(aggW + l * OO + o0);

        float* outp = g_agg + (row0 + rq * 16) * (size_t)OO + o0;
#pragma unroll
        for (int rr = 0; rr < 16; rr++) {
            const int r = rq * 16 + rr;
            float ax = 0.f, ay = 0.f, az = 0.f, aw = 0.f;
#pragma unroll
            for (int l = 0; l < LL; l++) {
                const float a = as_[r][l];
                ax += a * wc[l].x; ay += a * wc[l].y;
                az += a * wc[l].z; aw += a * wc[l].w;
            }
            float4 o4; o4.x = ax; o4.y = ay; o4.z = az; o4.w = aw;
            *(float4*)(outp + (size_t)rr * OO) = o4;
        }
    }
}

// ---------------------------------------------------------------------------
// Kernel 2: recurrence, batch-staggered. PH1 = the R11 FMA block for ONE
// batch (accs folded + partials stored); PH2 = reduce-and-publish for the
// OTHER batch, overlapped inside the same barrier segment.
// ---------------------------------------------------------------------------
#define PH1(sX, pwX)                                                            \
    do {                                                                        \
        unsigned long long acc0 = 0, acc1 = 0, acc2 = 0, acc3 = 0;              \
        _Pragma("unroll")                                                       \
        for (int ii = 0; ii < 12; ii++) {                                       \
            unsigned long long ax, ay;                                          \
            lds_v2u64(ax, ay, (sX) + ii * 16);                                  \
            FMA2(acc0, ax, Rp[(2*ii)*4+0]);                                     \
            FMA2(acc1, ax, Rp[(2*ii)*4+1]);                                     \
            FMA2(acc2, ax, Rp[(2*ii)*4+2]);                                     \
            FMA2(acc3, ax, Rp[(2*ii)*4+3]);                                     \
            FMA2(acc0, ay, Rp[(2*ii+1)*4+0]);                                   \
            FMA2(acc1, ay, Rp[(2*ii+1)*4+1]);                                   \
            FMA2(acc2, ay, Rp[(2*ii+1)*4+2]);                                   \
            FMA2(acc3, ay, Rp[(2*ii+1)*4+3]);                                   \
        }                                                                       \
        _Pragma("unroll")                                                       \
        for (int q = 0; q < 4; q++) {                                           \
            unsigned long long ax, ay, r0, r1, r2, r3;                          \
            lds_v2u64(ax, ay, (sX) + (12 + q) * 16);                            \
            lds_v2u64(r0, r1, rsm + (2*q) * 32);                                \
            lds_v2u64(r2, r3, rsm + (2*q) * 32 + 16);                           \
            FMA2(acc0, ax, r0); FMA2(acc1, ax, r1);                             \
            FMA2(acc2, ax, r2); FMA2(acc3, ax, r3);                             \
            lds_v2u64(r0, r1, rsm + (2*q+1) * 32);                              \
            lds_v2u64(r2, r3, rsm + (2*q+1) * 32 + 16);                         \
            FMA2(acc0, ay, r0); FMA2(acc1, ay, r1);                             \
            FMA2(acc2, ay, r2); FMA2(acc3, ay, r3);                             \
        }                                                                       \
        float fx, fy;                                                           \
        asm("mov.b64 {%0,%1}, %2;" : "=f"(fx), "=f"(fy) : "l"(acc0));           \
        sts_f32((pwX) + 0*128, fx + fy);                                        \
        asm("mov.b64 {%0,%1}, %2;" : "=f"(fx), "=f"(fy) : "l"(acc1));           \
        sts_f32((pwX) + 1*128, fx + fy);                                        \
        asm("mov.b64 {%0,%1}, %2;" : "=f"(fx), "=f"(fy) : "l"(acc2));           \
        sts_f32((pwX) + 2*128, fx + fy);                                        \
        asm("mov.b64 {%0,%1}, %2;" : "=f"(fx), "=f"(fy) : "l"(acc3));           \
        sts_f32((pwX) + 3*128, fx + fy);                                        \
    } while (0)

__global__ void __launch_bounds__(NTHR, 1) recur_kernel(const float* __restrict__ R,
                                                        float* __restrict__ out)
{
    extern __shared__ unsigned char dyn[];
    unsigned int sm;
    asm("{ .reg .u64 t0; cvta.to.shared.u64 t0, %1; cvt.u32.u64 %0, t0; }"
        : "=r"(sm) : "l"(dyn));

    const int tid  = threadIdx.x;
    const int lane = tid & 31;
    const int w    = tid >> 5;
    const int c    = w & 3;        // k-chunk: rows 64c .. 64c+63
    const int h    = w >> 2;       // o-half
    const int b0   = blockIdx.x * 2;

    // ---- 24 k-pairs (48 rows) x 4 o-cols into registers
    unsigned long long Rp[24 * 4];
#pragma unroll
    for (int i = 0; i < 24; i++)
#pragma unroll
        for (int j = 0; j < 4; j++) {
            const int k = c * 64 + 2 * i;
            const int o = h * 128 + lane + 32 * j;
            float lo = R[(size_t)k * OO + o];
            float hi = R[(size_t)(k + 1) * OO + o];
            asm("mov.b64 %0, {%1, %2};" : "=l"(Rp[i * 4 + j]) : "f"(lo), "f"(hi));
        }

    // ---- 8 k-pairs (16 rows) x 4 o-cols into per-thread smem rows
    const unsigned int rsm = sm + RSM_OFF + tid * RSM_TSTRIDE;
#pragma unroll
    for (int i = 0; i < 8; i++)
#pragma unroll
        for (int j = 0; j < 4; j++) {
            const int k = c * 64 + 48 + 2 * i;
            const int o = h * 128 + lane + 32 * j;
            float lo = R[(size_t)k * OO + o];
            float hi = R[(size_t)(k + 1) * OO + o];
            unsigned long long p;
            asm("mov.b64 %0, {%1, %2};" : "=l"(p) : "f"(lo), "f"(hi));
            sts_u64(rsm + (unsigned)(i * 4 + j) * 8, p);
        }

    // zero initial state (2 batches x 256, single-buffered)
    sts_f32(sm + S_OFF + 0 * 1024 + tid * 4, 0.f);
    sts_f32(sm + S_OFF + 1 * 1024 + tid * 4, 0.f);

    // identities
    const float* aggp0 = g_agg + ((size_t)b0       * TT) * OO + tid;
    const float* aggp1 = g_agg + ((size_t)(b0 + 1) * TT) * OO + tid;
    float*       outp0 = out   + ((size_t)b0       * TT) * OO + tid;
    float*       outp1 = out   + ((size_t)(b0 + 1) * TT) * OO + tid;

    // addresses
    const unsigned int sA  = sm + S_OFF + c * 256;           // phase-1 state reads, batch A
    const unsigned int sB  = sA + 1024;                      // batch B
    const unsigned int pwA = sm + PA_OFF + c * 1024 + (h * 128 + lane) * 4;
    const unsigned int pwB = sm + PB_OFF + c * 1024 + (h * 128 + lane) * 4;
    const unsigned int prA = sm + PA_OFF + tid * 4;
    const unsigned int prB = sm + PB_OFF + tid * 4;
    const unsigned int swA = sm + S_OFF + tid * 4;            // phase-2 state writes
    const unsigned int swB = swA + 1024;

    float a_A = __ldg(aggp0);     // agg_A(0)
    float a_B = __ldg(aggp1);     // agg_B(0)

    __syncthreads();

    // ---- prologue: phase1_A(0) on zero state
    PH1(sA, pwA);
    __syncthreads();

    for (int t = 0; t < TT; t++) {
        // ======== segment B: phase1_B(t) + phase2_A(t) ========
        const float a_An = __ldg(aggp0 + (size_t)(t + 1) * OO);   // agg_A(t+1)
        // phase-2 partial loads issued before the FMA block (ready since barrier)
        const float pA0 = lds_f32(prA + 0*1024);
        const float pA1 = lds_f32(prA + 1*1024);
        const float pA2 = lds_f32(prA + 2*1024);
        const float pA3 = lds_f32(prA + 3*1024);

        PH1(sB, pwB);

        {
            const float r0 = a_A + ((pA0 + pA1) + (pA2 + pA3));   // s_A(t)
            sts_f32(swA, r0);
            *outp0 = r0; outp0 += OO;
        }
        __syncthreads();

        // ======== segment A: phase1_A(t+1) + phase2_B(t) ========
        const float a_Bn = __ldg(aggp1 + (size_t)(t + 1) * OO);   // agg_B(t+1)
        const float pB0 = lds_f32(prB + 0*1024);
        const float pB1 = lds_f32(prB + 1*1024);
        const float pB2 = lds_f32(prB + 2*1024);
        const float pB3 = lds_f32(prB + 3*1024);

        PH1(sA, pwA);    // at t = TT-1 this is dead work (partials never read)

        {
            const float r1 = a_B + ((pB0 + pB1) + (pB2 + pB3));   // s_B(t)
            sts_f32(swB, r1);
            *outp1 = r1; outp1 += OO;
        }
        __syncthreads();

        a_A = a_An; a_B = a_Bn;
    }
}

// ---------------------------------------------------------------------------
extern "C" void kernel_launch(void* const* d_in, const int* in_sizes, int n_in,
                              void* d_out, int out_size)
{
    const float* x    = (const float*)d_in[0];
    const float* subW = (const float*)d_in[1];
    const float* subb = (const float*)d_in[2];
    const float* aggW = (const float*)d_in[3];
    const float* R    = (const float*)d_in[4];
    float* out = (float*)d_out;

    cudaFuncSetAttribute(recur_kernel, cudaFuncAttributeMaxDynamicSharedMemorySize,
                         SMEM_BYTES);

    act_agg_kernel<<<(BB * TT) / 64, 256>>>(x, subW, subb, aggW);
    recur_kernel<<<BB / 2, NTHR, SMEM_BYTES>>>(R, out);
}

// round 14
// speedup vs baseline: 1.2057x; 1.2057x over previous
#include <cuda_runtime.h>

#define BB 256
#define TT 1024
#define DD 128
#define LL 16
#define OO 256

// ---- recurrence geometry (R11 tiling — best measured): 256 thr = 8 warps =
// 4 k-chunks x 2 o-halves; thread: 64 k x 4 o; 48 k in regs, 16 k via smem.
#define NTHR 256
#define RSM_TSTRIDE 272     // 32 u64 data + 2 u64 pad per thread

#define PART_OFF 0          // partial[4 chunk][2 batch][256 o] f32 = 8 KB
#define S_OFF    8192       // state [2 parity][2 batch][256] f32  = 4 KB
#define RSM_OFF  12288      // Rsm: 256 * 272 = 69632 B
#define SMEM_BYTES (RSM_OFF + NTHR * RSM_TSTRIDE)   // 81920 B

// +OO pad: recur prefetches agg[t+1] unconditionally at t = TT-1.
__device__ float g_agg[(size_t)BB * TT * OO + OO];

#define FMA2(acc, a, b) asm("fma.rn.f32x2 %0, %1, %2, %0;" : "+l"(acc) : "l"(a), "l"(b))
#define ADD2(d, a, b)   asm("add.rn.f32x2 %0, %1, %2;" : "=l"(d) : "l"(a), "l"(b))

__device__ __forceinline__ void lds_v2u64(unsigned long long& a, unsigned long long& b,
                                          unsigned int addr) {
    asm volatile("ld.shared.v2.u64 {%0, %1}, [%2];" : "=l"(a), "=l"(b) : "r"(addr));
}
__device__ __forceinline__ unsigned long long lds_u64(unsigned int addr) {
    unsigned long long v;
    asm volatile("ld.shared.u64 %0, [%1];" : "=l"(v) : "r"(addr)); return v;
}
__device__ __forceinline__ void sts_f32(unsigned int addr, float v) {
    asm volatile("st.shared.f32 [%0], %1;" :: "r"(addr), "f"(v));
}
__device__ __forceinline__ void sts_u64(unsigned int addr, unsigned long long v) {
    asm volatile("st.shared.u64 [%0], %1;" :: "r"(addr), "l"(v));
}
__device__ __forceinline__ unsigned long long ldg_u64(const float* p) {
    unsigned long long v;
    asm volatile("ld.global.nc.b64 %0, [%1];" : "=l"(v) : "l"(p)); return v;
}
__device__ __forceinline__ void stg_u64(float* p, unsigned long long v) {
    asm volatile("st.global.b64 [%0], %1;" :: "l"(p), "l"(v) : "memory");
}

// ---------------------------------------------------------------------------
// Kernel 1: agg[b,t,o] — R11 VERBATIM (measured 159 us).
// ---------------------------------------------------------------------------
__global__ void __launch_bounds__(256) act_agg_kernel(
    const float* __restrict__ x, const float* __restrict__ subW,
    const float* __restrict__ subb, const float* __restrict__ aggW)
{
    __shared__ float xs[64][DD];
    __shared__ float ws[LL][DD + 4];
    __shared__ float as_[64][LL + 1];

    const int tid = threadIdx.x;
    const size_t row0 = (size_t)blockIdx.x * 64;

    for (int i = tid; i < LL * DD; i += 256) ws[i / DD][i % DD] = subW[i];
    {
        const float4* xg = (const float4*)(x + row0 * DD);
        float4* xs4 = (float4*)&xs[0][0];
#pragma unroll
        for (int i = 0; i < 8; i++) xs4[tid + 256 * i] = xg[tid + 256 * i];
    }
    __syncthreads();

    {
        const int l = tid & 15;
        const int rb = tid >> 4;
        const float bias = subb[l];
        const ulonglong2* wr = (const ulonglong2*)&ws[l][0];
#pragma unroll
        for (int it = 0; it < 4; it++) {
            const int r = rb + 16 * it;
            const ulonglong2* xr = (const ulonglong2*)&xs[r][0];
            unsigned long long acc = 0ULL;
#pragma unroll
            for (int i = 0; i < 32; i++) {
                ulonglong2 a = xr[i], b = wr[i];
                FMA2(acc, a.x, b.x);
                FMA2(acc, a.y, b.y);
            }
            float lo, hi;
            asm("mov.b64 {%0, %1}, %2;" : "=f"(lo), "=f"(hi) : "l"(acc));
            const float s = lo + hi + bias;
            float v;
            const int m = l & 3;
            if (m == 0)      v = tanhf(s);
            else if (m == 1) v = fmaxf(s, 0.f);
            else if (m == 2) v = 1.f / (1.f + expf(-s));
            else             v = s;
            as_[r][l] = v;
        }
    }
    __syncthreads();

    {
        const int oq = tid & 63;
        const int rq = tid >> 6;
        const int o0 = oq * 4;
        float4 wc[LL];
#pragma unroll
        for (int l = 0; l < LL; l++) wc[l] = *(const float4*)(aggW + l * OO + o0);

        float* outp = g_agg + (row0 + rq * 16) * (size_t)OO + o0;
#pragma unroll
        for (int rr = 0; rr < 16; rr++) {
            const int r = rq * 16 + rr;
            float ax = 0.f, ay = 0.f, az = 0.f, aw = 0.f;
#pragma unroll
            for (int l = 0; l < LL; l++) {
                const float a = as_[r][l];
                ax += a * wc[l].x; ay += a * wc[l].y;
                az += a * wc[l].z; aw += a * wc[l].w;
            }
            float4 o4; o4.x = ax; o4.y = ay; o4.z = az; o4.w = aw;
            *(float4*)(outp + (size_t)rr * OO) = o4;
        }
    }
}

// ---------------------------------------------------------------------------
// Kernel 2: recurrence s_t = agg_t + s_{t-1} @ R.
// Phase-1 and all layouts are R11 VERBATIM. Phase-2 remapped: thread =
// (o-pair, batch) -> 4x LDS.64 + packed f32x2 adds + STS.64 + STG.64.
// Loop manually unrolled 2x with hardcoded parity offsets.
// ---------------------------------------------------------------------------
__global__ void __launch_bounds__(NTHR, 1) recur_kernel(const float* __restrict__ R,
                                                        float* __restrict__ out)
{
    extern __shared__ unsigned char dyn[];
    unsigned int sm;
    asm("{ .reg .u64 t0; cvta.to.shared.u64 t0, %1; cvt.u32.u64 %0, t0; }"
        : "=r"(sm) : "l"(dyn));

    const int tid  = threadIdx.x;
    const int lane = tid & 31;
    const int w    = tid >> 5;
    const int c    = w & 3;        // k-chunk: rows 64c .. 64c+63
    const int h    = w >> 2;       // o-half
    const int b0   = blockIdx.x * 2;

    // ---- 24 k-pairs (48 rows) x 4 o-cols into registers
    unsigned long long Rp[24 * 4];
#pragma unroll
    for (int i = 0; i < 24; i++)
#pragma unroll
        for (int j = 0; j < 4; j++) {
            const int k = c * 64 + 2 * i;
            const int o = h * 128 + lane + 32 * j;
            float lo = R[(size_t)k * OO + o];
            float hi = R[(size_t)(k + 1) * OO + o];
            asm("mov.b64 %0, {%1, %2};" : "=l"(Rp[i * 4 + j]) : "f"(lo), "f"(hi));
        }

    // ---- 8 k-pairs (16 rows) x 4 o-cols into per-thread smem rows
    const unsigned int rsm = sm + RSM_OFF + tid * RSM_TSTRIDE;
#pragma unroll
    for (int i = 0; i < 8; i++)
#pragma unroll
        for (int j = 0; j < 4; j++) {
            const int k = c * 64 + 48 + 2 * i;
            const int o = h * 128 + lane + 32 * j;
            float lo = R[(size_t)k * OO + o];
            float hi = R[(size_t)(k + 1) * OO + o];
            unsigned long long p;
            asm("mov.b64 %0, {%1, %2};" : "=l"(p) : "f"(lo), "f"(hi));
            sts_u64(rsm + (unsigned)(i * 4 + j) * 8, p);
        }

    // ---- phase-2 identity: thread = (o-pair op, batch bt)
    const int op = tid & 127;      // o columns 2*op, 2*op+1
    const int bt = tid >> 7;

    // zero initial state, parity-0 buffer: each thread zeros its own slot
    sts_u64(sm + S_OFF + bt * 1024 + op * 8, 0ULL);

    const float* aggp  = g_agg + ((size_t)(b0 + bt) * TT) * OO + 2 * op;
    const float* aggpn = aggp + OO;                    // prefetch cursor (t+1)
    float*       outp  = out   + ((size_t)(b0 + bt) * TT) * OO + 2 * op;
    unsigned long long a_cur = ldg_u64(aggp);          // (agg[o0], agg[o1]) at t=0

    // addresses
    const unsigned int schunk = sm + S_OFF + c * 256;                        // phase-1 reads
    const unsigned int pw     = sm + PART_OFF + c * 2048 + (h * 128 + lane) * 4;
    const unsigned int prb    = sm + PART_OFF + bt * 1024 + op * 8;          // + c*2048
    const unsigned int swb    = sm + S_OFF + bt * 1024 + op * 8;             // + parity*2048

    __syncthreads();

    // One full timestep. SR = read-parity byte offset, SW = write-parity offset.
#define RSTEP(SR, SW)                                                           \
    {                                                                           \
        const unsigned long long a_nxt = ldg_u64(aggpn); aggpn += OO;           \
        const unsigned int sA = schunk + (SR);                                  \
        const unsigned int sB = sA + 1024;                                      \
        unsigned long long acc0 = 0, acc1 = 0, acc2 = 0, acc3 = 0,              \
                           acc4 = 0, acc5 = 0, acc6 = 0, acc7 = 0;              \
        _Pragma("unroll")                                                       \
        for (int ii = 0; ii < 12; ii++) {                                       \
            unsigned long long ax, ay, bx, by;                                  \
            lds_v2u64(ax, ay, sA + ii * 16);                                    \
            lds_v2u64(bx, by, sB + ii * 16);                                    \
            FMA2(acc0, ax, Rp[(2*ii)*4+0]);   FMA2(acc4, bx, Rp[(2*ii)*4+0]);   \
            FMA2(acc1, ax, Rp[(2*ii)*4+1]);   FMA2(acc5, bx, Rp[(2*ii)*4+1]);   \
            FMA2(acc2, ax, Rp[(2*ii)*4+2]);   FMA2(acc6, bx, Rp[(2*ii)*4+2]);   \
            FMA2(acc3, ax, Rp[(2*ii)*4+3]);   FMA2(acc7, bx, Rp[(2*ii)*4+3]);   \
            FMA2(acc0, ay, Rp[(2*ii+1)*4+0]); FMA2(acc4, by, Rp[(2*ii+1)*4+0]); \
            FMA2(acc1, ay, Rp[(2*ii+1)*4+1]); FMA2(acc5, by, Rp[(2*ii+1)*4+1]); \
            FMA2(acc2, ay, Rp[(2*ii+1)*4+2]); FMA2(acc6, by, Rp[(2*ii+1)*4+2]); \
            FMA2(acc3, ay, Rp[(2*ii+1)*4+3]); FMA2(acc7, by, Rp[(2*ii+1)*4+3]); \
        }                                                                       \
        _Pragma("unroll")                                                       \
        for (int q = 0; q < 4; q++) {                                           \
            unsigned long long ax, ay, bx, by, r0, r1, r2, r3;                  \
            lds_v2u64(ax, ay, sA + (12 + q) * 16);                              \
            lds_v2u64(bx, by, sB + (12 + q) * 16);                              \
            lds_v2u64(r0, r1, rsm + (2*q) * 32);                                \
            lds_v2u64(r2, r3, rsm + (2*q) * 32 + 16);                           \
            FMA2(acc0, ax, r0); FMA2(acc4, bx, r0);                             \
            FMA2(acc1, ax, r1); FMA2(acc5, bx, r1);                             \
            FMA2(acc2, ax, r2); FMA2(acc6, bx, r2);                             \
            FMA2(acc3, ax, r3); FMA2(acc7, bx, r3);                             \
            lds_v2u64(r0, r1, rsm + (2*q+1) * 32);                              \
            lds_v2u64(r2, r3, rsm + (2*q+1) * 32 + 16);                         \
            FMA2(acc0, ay, r0); FMA2(acc4, by, r0);                             \
            FMA2(acc1, ay, r1); FMA2(acc5, by, r1);                             \
            FMA2(acc2, ay, r2); FMA2(acc6, by, r2);                             \
            FMA2(acc3, ay, r3); FMA2(acc7, by, r3);                             \
        }                                                                       \
        {   /* fold even/odd-k halves, store 8 partials (coalesced STS.32) */   \
            float fx, fy;                                                       \
            asm("mov.b64 {%0,%1}, %2;" : "=f"(fx), "=f"(fy) : "l"(acc0));       \
            sts_f32(pw + 0*1024 + 0*128, fx + fy);                              \
            asm("mov.b64 {%0,%1}, %2;" : "=f"(fx), "=f"(fy) : "l"(acc1));       \
            sts_f32(pw + 0*1024 + 1*128, fx + fy);                              \
            asm("mov.b64 {%0,%1}, %2;" : "=f"(fx), "=f"(fy) : "l"(acc2));       \
            sts_f32(pw + 0*1024 + 2*128, fx + fy);                              \
            asm("mov.b64 {%0,%1}, %2;" : "=f"(fx), "=f"(fy) : "l"(acc3));       \
            sts_f32(pw + 0*1024 + 3*128, fx + fy);                              \
            asm("mov.b64 {%0,%1}, %2;" : "=f"(fx), "=f"(fy) : "l"(acc4));       \
            sts_f32(pw + 1*1024 + 0*128, fx + fy);                              \
            asm("mov.b64 {%0,%1}, %2;" : "=f"(fx), "=f"(fy) : "l"(acc5));       \
            sts_f32(pw + 1*1024 + 1*128, fx + fy);                              \
            asm("mov.b64 {%0,%1}, %2;" : "=f"(fx), "=f"(fy) : "l"(acc6));       \
            sts_f32(pw + 1*1024 + 2*128, fx + fy);                              \
            asm("mov.b64 {%0,%1}, %2;" : "=f"(fx), "=f"(fy) : "l"(acc7));       \
            sts_f32(pw + 1*1024 + 3*128, fx + fy);                              \
        }                                                                       \
        __syncthreads();                                                        \
        {   /* phase 2: o-pair reduce via packed adds (same fp order) */        \
            unsigned long long r = a_cur;                                       \
            ADD2(r, r, lds_u64(prb + 0*2048));                                  \
            ADD2(r, r, lds_u64(prb + 1*2048));                                  \
            ADD2(r, r, lds_u64(prb + 2*2048));                                  \
            ADD2(r, r, lds_u64(prb + 3*2048));                                  \
            sts_u64(swb + (SW), r);                                             \
            stg_u64(outp, r); outp += OO;                                       \
        }                                                                       \
        a_cur = a_nxt;                                                          \
        __syncthreads();                                                        \
    }

    for (int t = 0; t < TT; t += 2) {
        RSTEP(0, 2048);      // even step: read parity 0, write parity 1
        RSTEP(2048, 0);      // odd step:  read parity 1, write parity 0
    }
#undef RSTEP
}

// ---------------------------------------------------------------------------
extern "C" void kernel_launch(void* const* d_in, const int* in_sizes, int n_in,
                              void* d_out, int out_size)
{
    const float* x    = (const float*)d_in[0];
    const float* subW = (const float*)d_in[1];
    const float* subb = (const float*)d_in[2];
    const float* aggW = (const float*)d_in[3];
    const float* R    = (const float*)d_in[4];
    float* out = (float*)d_out;

    cudaFuncSetAttribute(recur_kernel, cudaFuncAttributeMaxDynamicSharedMemorySize,
                         SMEM_BYTES);

    act_agg_kernel<<<(BB * TT) / 64, 256>>>(x, subW, subb, aggW);
    recur_kernel<<<BB / 2, NTHR, SMEM_BYTES>>>(R, out);
}